// round 1
// baseline (speedup 1.0000x reference)
#include <cuda_runtime.h>
#include <cuda_bf16.h>
#include <math.h>

#define HD 2048
#define ID 1408
#define NE 8
#define NT 8192
#define NP (NT*2)

// ---- scratch (device globals; allocation-free per harness rules) ----
__device__ int   g_cnt[NE];
__device__ int   g_list[NE * NP];
__device__ int   g_eid[NP];
__device__ float g_pw[NP];
__device__ float g_act[(size_t)NP * ID];   // ~92 MB
__device__ float g_y2 [(size_t)NP * HD];   // ~134 MB

// ============================================================
// Kernel 1: router logits + top-2 + softmax weights. One warp per token.
// Also zeroes the expert counters (used by the next launch).
// ============================================================
__global__ __launch_bounds__(256) void router_kernel(
    const float* __restrict__ x, const float* __restrict__ rw)
{
    int tid = threadIdx.x;
    if (blockIdx.x == 0 && tid < NE) g_cnt[tid] = 0;

    int warp = tid >> 5, lane = tid & 31;
    int t = blockIdx.x * 8 + warp;
    if (t >= NT) return;

    const float* xt = x + (size_t)t * HD;
    float acc[NE];
#pragma unroll
    for (int e = 0; e < NE; e++) acc[e] = 0.f;

    for (int h = lane; h < HD; h += 32) {
        float xv = xt[h];
#pragma unroll
        for (int e = 0; e < NE; e++)
            acc[e] += xv * __ldg(rw + e * HD + h);
    }
#pragma unroll
    for (int off = 16; off; off >>= 1) {
#pragma unroll
        for (int e = 0; e < NE; e++)
            acc[e] += __shfl_xor_sync(0xffffffffu, acc[e], off);
    }
    if (lane == 0) {
        int i0 = 0; float v0 = acc[0];
#pragma unroll
        for (int e = 1; e < NE; e++)
            if (acc[e] > v0) { v0 = acc[e]; i0 = e; }   // strict > : lowest idx on tie (jax top_k)
        int i1 = -1; float v1 = -1e30f;
#pragma unroll
        for (int e = 0; e < NE; e++)
            if (e != i0 && acc[e] > v1) { v1 = acc[e]; i1 = e; }
        float w0 = 1.f / (1.f + expf(v1 - v0));  // softmax over [v0, v1], v0 >= v1
        g_eid[2*t]   = i0;  g_eid[2*t+1] = i1;
        g_pw [2*t]   = w0;  g_pw [2*t+1] = 1.f - w0;
    }
}

// ============================================================
// Kernel 2: scatter pairs into per-expert lists
// ============================================================
__global__ __launch_bounds__(256) void assign_kernel()
{
    int p = blockIdx.x * blockDim.x + threadIdx.x;
    if (p < NP) {
        int e = g_eid[p];
        int pos = atomicAdd(&g_cnt[e], 1);
        g_list[e * NP + pos] = p;
    }
}

// ============================================================
// Kernel 3: grouped GEMM1 (gate+up fused) + SwiGLU epilogue
// Tile: 128(M) x 64(N over I) x 8(K over H). 256 threads, 8x4 per thread x2.
// ============================================================
__global__ __launch_bounds__(256) void gemm1_kernel(
    const float* __restrict__ x, const float* __restrict__ w1)
{
    const int e = blockIdx.z;
    const int cnt = g_cnt[e];
    const int m0 = blockIdx.y * 128;
    if (m0 >= cnt) return;
    const int n0 = blockIdx.x * 64;

    __shared__ float As[8][128];
    __shared__ float Bg[8][64];
    __shared__ float Bu[8][64];
    __shared__ int   sp[128];

    const int tid = threadIdx.x;
    if (tid < 128) {
        int m = m0 + tid;
        sp[tid] = (m < cnt) ? g_list[e * NP + m] : -1;
    }
    __syncthreads();

    const int tidm = tid >> 4, tidn = tid & 15;

    float accg[8][4], accu[8][4];
#pragma unroll
    for (int i = 0; i < 8; i++)
#pragma unroll
        for (int j = 0; j < 4; j++) { accg[i][j] = 0.f; accu[i][j] = 0.f; }

    // A-load indices: 128 rows x 8 k = 256 float4
    const int ar = tid >> 1;
    const int ah = (tid & 1) * 4;
    const int pa = sp[ar];
    const float* arow = (pa >= 0) ? (x + (size_t)(pa >> 1) * HD) : x;

    // B-load: gate (tid<128) / up (tid>=128), each 64 rows x 8 k = 128 float4
    const int bw = tid >> 7;
    const int bi = tid & 127;
    const int bn = bi >> 1;
    const int bh = (bi & 1) * 4;
    const float* w1e = w1 + (size_t)e * 2 * ID * HD;
    const float* brow = w1e + (size_t)(bw * ID + n0 + bn) * HD;

    for (int k0 = 0; k0 < HD; k0 += 8) {
        float4 av = make_float4(0.f, 0.f, 0.f, 0.f);
        if (pa >= 0) av = *reinterpret_cast<const float4*>(arow + k0 + ah);
        As[ah+0][ar] = av.x; As[ah+1][ar] = av.y;
        As[ah+2][ar] = av.z; As[ah+3][ar] = av.w;

        float4 bv = *reinterpret_cast<const float4*>(brow + k0 + bh);
        float* Bdst = bw ? &Bu[0][0] : &Bg[0][0];
        Bdst[(bh+0)*64 + bn] = bv.x; Bdst[(bh+1)*64 + bn] = bv.y;
        Bdst[(bh+2)*64 + bn] = bv.z; Bdst[(bh+3)*64 + bn] = bv.w;
        __syncthreads();

#pragma unroll
        for (int k = 0; k < 8; k++) {
            float fa[8], fg[4], fu[4];
#pragma unroll
            for (int i = 0; i < 8; i++) fa[i] = As[k][tidm*8 + i];
#pragma unroll
            for (int j = 0; j < 4; j++) { fg[j] = Bg[k][tidn*4 + j]; fu[j] = Bu[k][tidn*4 + j]; }
#pragma unroll
            for (int i = 0; i < 8; i++)
#pragma unroll
                for (int j = 0; j < 4; j++) {
                    accg[i][j] += fa[i] * fg[j];
                    accu[i][j] += fa[i] * fu[j];
                }
        }
        __syncthreads();
    }

#pragma unroll
    for (int i = 0; i < 8; i++) {
        int p = sp[tidm*8 + i];
        if (p >= 0) {
            float* dst = g_act + (size_t)p * ID + n0 + tidn*4;
#pragma unroll
            for (int j = 0; j < 4; j++) {
                float g = accg[i][j], u = accu[i][j];
                float s = g / (1.f + expf(-g));   // silu
                dst[j] = s * u;
            }
        }
    }
}

// ============================================================
// Kernel 4: grouped GEMM2 (down proj). 128x128x8 tile, 8x8 per thread.
// ============================================================
__global__ __launch_bounds__(256) void gemm2_kernel(const float* __restrict__ w2)
{
    const int e = blockIdx.z;
    const int cnt = g_cnt[e];
    const int m0 = blockIdx.y * 128;
    if (m0 >= cnt) return;
    const int n0 = blockIdx.x * 128;

    __shared__ float As[8][128];
    __shared__ float Bs[8][128];
    __shared__ int   sp[128];

    const int tid = threadIdx.x;
    if (tid < 128) {
        int m = m0 + tid;
        sp[tid] = (m < cnt) ? g_list[e * NP + m] : -1;
    }
    __syncthreads();

    const int ty = tid >> 4, tx = tid & 15;

    float acc[8][8];
#pragma unroll
    for (int i = 0; i < 8; i++)
#pragma unroll
        for (int j = 0; j < 8; j++) acc[i][j] = 0.f;

    const int ar = tid >> 1;
    const int ah = (tid & 1) * 4;
    const int pa = sp[ar];
    const float* arow = (pa >= 0) ? (g_act + (size_t)pa * ID) : g_act;

    const int br = tid >> 1;      // n row 0..127
    const int bh = (tid & 1) * 4; // k offset
    const float* brow = w2 + (size_t)e * HD * ID + (size_t)(n0 + br) * ID;

    for (int k0 = 0; k0 < ID; k0 += 8) {
        float4 av = make_float4(0.f, 0.f, 0.f, 0.f);
        if (pa >= 0) av = *reinterpret_cast<const float4*>(arow + k0 + ah);
        As[ah+0][ar] = av.x; As[ah+1][ar] = av.y;
        As[ah+2][ar] = av.z; As[ah+3][ar] = av.w;

        float4 bv = *reinterpret_cast<const float4*>(brow + k0 + bh);
        Bs[bh+0][br] = bv.x; Bs[bh+1][br] = bv.y;
        Bs[bh+2][br] = bv.z; Bs[bh+3][br] = bv.w;
        __syncthreads();

#pragma unroll
        for (int k = 0; k < 8; k++) {
            float fa[8], fb[8];
#pragma unroll
            for (int i = 0; i < 8; i++) fa[i] = As[k][ty*8 + i];
#pragma unroll
            for (int j = 0; j < 8; j++) fb[j] = Bs[k][tx*8 + j];
#pragma unroll
            for (int i = 0; i < 8; i++)
#pragma unroll
                for (int j = 0; j < 8; j++) acc[i][j] += fa[i] * fb[j];
        }
        __syncthreads();
    }

#pragma unroll
    for (int i = 0; i < 8; i++) {
        int p = sp[ty*8 + i];
        if (p >= 0) {
            float* dst = g_y2 + (size_t)p * HD + n0 + tx*8;
#pragma unroll
            for (int j = 0; j < 8; j++) dst[j] = acc[i][j];
        }
    }
}

// ============================================================
// Kernel 5: combine pairs with routing weights -> output
// ============================================================
__global__ __launch_bounds__(256) void combine_kernel(float* __restrict__ out)
{
    size_t i = (size_t)blockIdx.x * blockDim.x + threadIdx.x;  // over NT*HD/4
    const size_t tot = (size_t)NT * HD / 4;
    if (i >= tot) return;
    int t = (int)(i / (HD/4));
    int r = (int)(i % (HD/4));
    float w0 = g_pw[2*t], w1v = g_pw[2*t+1];
    const float4* y2v = reinterpret_cast<const float4*>(g_y2);
    float4 a = y2v[(size_t)(2*t)   * (HD/4) + r];
    float4 b = y2v[(size_t)(2*t+1) * (HD/4) + r];
    float4 o;
    o.x = w0*a.x + w1v*b.x;
    o.y = w0*a.y + w1v*b.y;
    o.z = w0*a.z + w1v*b.z;
    o.w = w0*a.w + w1v*b.w;
    reinterpret_cast<float4*>(out)[i] = o;
}

// ============================================================
extern "C" void kernel_launch(void* const* d_in, const int* in_sizes, int n_in,
                              void* d_out, int out_size)
{
    const float* x  = (const float*)d_in[0];
    const float* rw = (const float*)d_in[1];
    const float* w1 = (const float*)d_in[2];
    const float* w2 = (const float*)d_in[3];
    float* out = (float*)d_out;

    router_kernel<<<NT/8, 256>>>(x, rw);
    assign_kernel<<<NP/256, 256>>>();
    gemm1_kernel<<<dim3(ID/64,  NP/128, NE), 256>>>(x, w1);
    gemm2_kernel<<<dim3(HD/128, NP/128, NE), 256>>>(w2);
    combine_kernel<<<(unsigned)(((size_t)NT*HD/4 + 255)/256), 256>>>(out);
}

// round 3
// speedup vs baseline: 1.8786x; 1.8786x over previous
#include <cuda_runtime.h>
#include <cuda_bf16.h>
#include <math.h>
#include <cstdint>

#define HD 2048
#define ID 1408
#define NE 8
#define NT 8192
#define NP (NT*2)

// ---- scratch (device globals) ----
__device__ int   g_cnt[NE];
__device__ int   g_list[NE * NP];
__device__ int   g_eid[NP];
__device__ float g_pw[NP];
__device__ float g_act[(size_t)NP * ID];   // ~92 MB
__device__ float g_y2 [(size_t)NP * HD];   // ~134 MB

__device__ __forceinline__ uint32_t tf32r(float f) {
    uint32_t r;
    asm("cvt.rna.tf32.f32 %0, %1;" : "=r"(r) : "f"(f));
    return r;
}

// m16n8k8 tf32 mma, fp32 accumulate
__device__ __forceinline__ void mma8(float* d, const uint32_t a0, const uint32_t a1,
                                     const uint32_t a2, const uint32_t a3,
                                     const uint32_t b0, const uint32_t b1) {
    asm volatile("mma.sync.aligned.m16n8k8.row.col.f32.tf32.tf32.f32 "
        "{%0,%1,%2,%3}, {%4,%5,%6,%7}, {%8,%9}, {%0,%1,%2,%3};"
        : "+f"(d[0]), "+f"(d[1]), "+f"(d[2]), "+f"(d[3])
        : "r"(a0), "r"(a1), "r"(a2), "r"(a3), "r"(b0), "r"(b1));
}

// SMEM layout (dynamic): sp[128] @0, A bufs @512 (2 x 16KB), B bufs @33280 (2 x 16KB)
#define SM_SP   0
#define SM_A(b) (512 + (b) * 16384)
#define SM_B(b) (33280 + (b) * 16384)
#define SMEM_BYTES 66048

// fragment-order staging indices
// A value (m, k): idx = ((m>>4)*4 + (k>>3))*128 + ((m&7)*4 + (k&3))*4 + ((k&7)>>2)*2 + ((m&15)>>3)
// B value (n, k): idx = ((n>>3)*4 + (k>>3))*64  + ((n&7)*4 + (k&3))*2 + ((k&7)>>2)

__device__ __forceinline__ void stageA(uint32_t* AS, int m, int f, float4 v) {
    int base = ((m >> 4) * 4 + (f >> 1)) * 128 + (m & 7) * 16 + (f & 1) * 2 + ((m & 15) >> 3);
    AS[base + 0]  = tf32r(v.x);
    AS[base + 4]  = tf32r(v.y);
    AS[base + 8]  = tf32r(v.z);
    AS[base + 12] = tf32r(v.w);
}
__device__ __forceinline__ void stageB(uint32_t* BS, int n, int f, float4 v) {
    int base = ((n >> 3) * 4 + (f >> 1)) * 64 + (n & 7) * 8 + (f & 1);
    BS[base + 0] = tf32r(v.x);
    BS[base + 2] = tf32r(v.y);
    BS[base + 4] = tf32r(v.z);
    BS[base + 6] = tf32r(v.w);
}

// ============================================================
// Kernel 1: router
// ============================================================
__global__ __launch_bounds__(256) void router_kernel(
    const float* __restrict__ x, const float* __restrict__ rw)
{
    int tid = threadIdx.x;
    if (blockIdx.x == 0 && tid < NE) g_cnt[tid] = 0;

    int warp = tid >> 5, lane = tid & 31;
    int t = blockIdx.x * 8 + warp;
    if (t >= NT) return;

    const float* xt = x + (size_t)t * HD;
    float acc[NE];
#pragma unroll
    for (int e = 0; e < NE; e++) acc[e] = 0.f;
    for (int h = lane; h < HD; h += 32) {
        float xv = xt[h];
#pragma unroll
        for (int e = 0; e < NE; e++) acc[e] += xv * __ldg(rw + e * HD + h);
    }
#pragma unroll
    for (int off = 16; off; off >>= 1)
#pragma unroll
        for (int e = 0; e < NE; e++) acc[e] += __shfl_xor_sync(0xffffffffu, acc[e], off);
    if (lane == 0) {
        int i0 = 0; float v0 = acc[0];
#pragma unroll
        for (int e = 1; e < NE; e++) if (acc[e] > v0) { v0 = acc[e]; i0 = e; }
        int i1 = -1; float v1 = -1e30f;
#pragma unroll
        for (int e = 0; e < NE; e++) if (e != i0 && acc[e] > v1) { v1 = acc[e]; i1 = e; }
        float w0 = 1.f / (1.f + expf(v1 - v0));
        g_eid[2*t] = i0; g_eid[2*t+1] = i1;
        g_pw[2*t] = w0;  g_pw[2*t+1] = 1.f - w0;
    }
}

// ============================================================
// Kernel 2: scatter pairs into per-expert lists
// ============================================================
__global__ __launch_bounds__(256) void assign_kernel()
{
    int p = blockIdx.x * blockDim.x + threadIdx.x;
    if (p < NP) {
        int e = g_eid[p];
        int pos = atomicAdd(&g_cnt[e], 1);
        g_list[e * NP + pos] = p;
    }
}

// ============================================================
// Kernel 3: grouped GEMM1 (gate+up interleaved) tf32 mma + SwiGLU
// Block tile: 128(M) x 128(B-rows: 64 gate + 64 up interleaved at n8) x 32(K)
// ============================================================
__global__ __launch_bounds__(256) void gemm1_tc(
    const float* __restrict__ x, const float* __restrict__ w1)
{
    const int e = blockIdx.z;
    const int cnt = g_cnt[e];
    const int m0 = blockIdx.y * 128;
    if (m0 >= cnt) return;
    const int n0a = blockIdx.x * 64;          // act cols [n0a, n0a+64)

    extern __shared__ char smem[];
    int* sp = (int*)(smem + SM_SP);

    const int tid = threadIdx.x;
    const int w = tid >> 5, lane = tid & 31;

    if (tid < 128) { int m = m0 + tid; sp[tid] = (m < cnt) ? g_list[e * NP + m] : -1; }
    __syncthreads();

    // gmem loaders: 8 lanes per 128B row chunk; rows rgrp+32j
    const int rgrp = tid >> 3;
    const int f = tid & 7;
    const float* arow[4];
    const float* brow[4];
    const float* w1e = w1 + (size_t)e * 2 * ID * HD;
#pragma unroll
    for (int j = 0; j < 4; j++) {
        int r = rgrp + 32 * j;
        int pa = sp[r];
        arow[j] = (pa >= 0 ? x + (size_t)(pa >> 1) * HD : x) + f * 4;
        int nt = r >> 3;
        int wrow = (nt & 1) * ID + n0a + (nt >> 1) * 8 + (r & 7);
        brow[j] = w1e + (size_t)wrow * HD + f * 4;
    }

    float acc[2][8][4];
#pragma unroll
    for (int i = 0; i < 2; i++)
#pragma unroll
        for (int n = 0; n < 8; n++)
#pragma unroll
            for (int c = 0; c < 4; c++) acc[i][n][c] = 0.f;

    float4 va[4], vb[4];
#pragma unroll
    for (int j = 0; j < 4; j++) { va[j] = *(const float4*)(arow[j]); vb[j] = *(const float4*)(brow[j]); }
    {   // stage chunk 0 -> buf 0
        uint32_t* AS = (uint32_t*)(smem + SM_A(0));
        uint32_t* BS = (uint32_t*)(smem + SM_B(0));
#pragma unroll
        for (int j = 0; j < 4; j++) { stageA(AS, rgrp + 32*j, f, va[j]); stageB(BS, rgrp + 32*j, f, vb[j]); }
    }
#pragma unroll
    for (int j = 0; j < 4; j++) { va[j] = *(const float4*)(arow[j] + 32); vb[j] = *(const float4*)(brow[j] + 32); }
    __syncthreads();

    const int mtg0 = (w >> 1) * 2;      // warp's first m16 tile
    const int bnt0 = (w & 1) * 8;       // warp's first n8 tile

    const int NC = HD / 32;
    for (int c = 0; c < NC; c++) {
        // stage chunk c+1 into buf (c+1)&1
        if (c + 1 < NC) {
            uint32_t* AS = (uint32_t*)(smem + SM_A((c + 1) & 1));
            uint32_t* BS = (uint32_t*)(smem + SM_B((c + 1) & 1));
#pragma unroll
            for (int j = 0; j < 4; j++) { stageA(AS, rgrp + 32*j, f, va[j]); stageB(BS, rgrp + 32*j, f, vb[j]); }
        }
        // prefetch chunk c+2
        if (c + 2 < NC) {
            int k = (c + 2) * 32;
#pragma unroll
            for (int j = 0; j < 4; j++) { va[j] = *(const float4*)(arow[j] + k); vb[j] = *(const float4*)(brow[j] + k); }
        }
        // compute buf c&1
        {
            const uint32_t* AS = (const uint32_t*)(smem + SM_A(c & 1));
            const uint32_t* BS = (const uint32_t*)(smem + SM_B(c & 1));
#pragma unroll
            for (int kt = 0; kt < 4; kt++) {
                uint4 a0 = *(const uint4*)(AS + ((mtg0 + 0) * 4 + kt) * 128 + lane * 4);
                uint4 a1 = *(const uint4*)(AS + ((mtg0 + 1) * 4 + kt) * 128 + lane * 4);
#pragma unroll
                for (int n = 0; n < 8; n++) {
                    uint2 bb = *(const uint2*)(BS + ((bnt0 + n) * 4 + kt) * 64 + lane * 2);
                    mma8(acc[0][n], a0.x, a0.y, a0.z, a0.w, bb.x, bb.y);
                    mma8(acc[1][n], a1.x, a1.y, a1.z, a1.w, bb.x, bb.y);
                }
            }
        }
        __syncthreads();
    }

    // epilogue: n8 tiles alternate gate/up -> silu(gate)*up in registers
    const int gid = lane >> 2, ctg = lane & 3;
#pragma unroll
    for (int mt = 0; mt < 2; mt++) {
        int r0 = (w >> 1) * 32 + mt * 16 + gid;
        int p0 = sp[r0];
        int p1 = sp[r0 + 8];
#pragma unroll
        for (int pi = 0; pi < 4; pi++) {
            float* g = acc[mt][2 * pi];
            float* u = acc[mt][2 * pi + 1];
            int col = n0a + ((w & 1) * 4 + pi) * 8 + 2 * ctg;
            if (p0 >= 0) {
                float g0 = g[0], g1 = g[1];
                float2 v = make_float2(u[0] * g0 / (1.f + expf(-g0)),
                                       u[1] * g1 / (1.f + expf(-g1)));
                *(float2*)(g_act + (size_t)p0 * ID + col) = v;
            }
            if (p1 >= 0) {
                float g2 = g[2], g3 = g[3];
                float2 v = make_float2(u[2] * g2 / (1.f + expf(-g2)),
                                       u[3] * g3 / (1.f + expf(-g3)));
                *(float2*)(g_act + (size_t)p1 * ID + col) = v;
            }
        }
    }
}

// ============================================================
// Kernel 4: grouped GEMM2 (down proj) tf32 mma
// Block tile: 128(M) x 128(N of HD) x 32(K of ID)
// ============================================================
__global__ __launch_bounds__(256) void gemm2_tc(const float* __restrict__ w2)
{
    const int e = blockIdx.z;
    const int cnt = g_cnt[e];
    const int m0 = blockIdx.y * 128;
    if (m0 >= cnt) return;
    const int n0 = blockIdx.x * 128;

    extern __shared__ char smem[];
    int* sp = (int*)(smem + SM_SP);

    const int tid = threadIdx.x;
    const int w = tid >> 5, lane = tid & 31;

    if (tid < 128) { int m = m0 + tid; sp[tid] = (m < cnt) ? g_list[e * NP + m] : -1; }
    __syncthreads();

    const int rgrp = tid >> 3;
    const int f = tid & 7;
    const float* arow[4];
    const float* brow[4];
    const float* w2e = w2 + (size_t)e * HD * ID;
#pragma unroll
    for (int j = 0; j < 4; j++) {
        int r = rgrp + 32 * j;
        int pa = sp[r];
        arow[j] = (pa >= 0 ? g_act + (size_t)pa * ID : g_act) + f * 4;
        brow[j] = w2e + (size_t)(n0 + r) * ID + f * 4;
    }

    float acc[2][8][4];
#pragma unroll
    for (int i = 0; i < 2; i++)
#pragma unroll
        for (int n = 0; n < 8; n++)
#pragma unroll
            for (int c = 0; c < 4; c++) acc[i][n][c] = 0.f;

    float4 va[4], vb[4];
#pragma unroll
    for (int j = 0; j < 4; j++) { va[j] = *(const float4*)(arow[j]); vb[j] = *(const float4*)(brow[j]); }
    {
        uint32_t* AS = (uint32_t*)(smem + SM_A(0));
        uint32_t* BS = (uint32_t*)(smem + SM_B(0));
#pragma unroll
        for (int j = 0; j < 4; j++) { stageA(AS, rgrp + 32*j, f, va[j]); stageB(BS, rgrp + 32*j, f, vb[j]); }
    }
#pragma unroll
    for (int j = 0; j < 4; j++) { va[j] = *(const float4*)(arow[j] + 32); vb[j] = *(const float4*)(brow[j] + 32); }
    __syncthreads();

    const int mtg0 = (w >> 1) * 2;
    const int bnt0 = (w & 1) * 8;

    const int NC = ID / 32;  // 44
    for (int c = 0; c < NC; c++) {
        if (c + 1 < NC) {
            uint32_t* AS = (uint32_t*)(smem + SM_A((c + 1) & 1));
            uint32_t* BS = (uint32_t*)(smem + SM_B((c + 1) & 1));
#pragma unroll
            for (int j = 0; j < 4; j++) { stageA(AS, rgrp + 32*j, f, va[j]); stageB(BS, rgrp + 32*j, f, vb[j]); }
        }
        if (c + 2 < NC) {
            int k = (c + 2) * 32;
#pragma unroll
            for (int j = 0; j < 4; j++) { va[j] = *(const float4*)(arow[j] + k); vb[j] = *(const float4*)(brow[j] + k); }
        }
        {
            const uint32_t* AS = (const uint32_t*)(smem + SM_A(c & 1));
            const uint32_t* BS = (const uint32_t*)(smem + SM_B(c & 1));
#pragma unroll
            for (int kt = 0; kt < 4; kt++) {
                uint4 a0 = *(const uint4*)(AS + ((mtg0 + 0) * 4 + kt) * 128 + lane * 4);
                uint4 a1 = *(const uint4*)(AS + ((mtg0 + 1) * 4 + kt) * 128 + lane * 4);
#pragma unroll
                for (int n = 0; n < 8; n++) {
                    uint2 bb = *(const uint2*)(BS + ((bnt0 + n) * 4 + kt) * 64 + lane * 2);
                    mma8(acc[0][n], a0.x, a0.y, a0.z, a0.w, bb.x, bb.y);
                    mma8(acc[1][n], a1.x, a1.y, a1.z, a1.w, bb.x, bb.y);
                }
            }
        }
        __syncthreads();
    }

    const int gid = lane >> 2, ctg = lane & 3;
#pragma unroll
    for (int mt = 0; mt < 2; mt++) {
        int r0 = (w >> 1) * 32 + mt * 16 + gid;
        int p0 = sp[r0];
        int p1 = sp[r0 + 8];
#pragma unroll
        for (int n = 0; n < 8; n++) {
            int col = n0 + ((w & 1) * 8 + n) * 8 + 2 * ctg;
            if (p0 >= 0)
                *(float2*)(g_y2 + (size_t)p0 * HD + col) = make_float2(acc[mt][n][0], acc[mt][n][1]);
            if (p1 >= 0)
                *(float2*)(g_y2 + (size_t)p1 * HD + col) = make_float2(acc[mt][n][2], acc[mt][n][3]);
        }
    }
}

// ============================================================
// Kernel 5: combine
// ============================================================
__global__ __launch_bounds__(256) void combine_kernel(float* __restrict__ out)
{
    size_t i = (size_t)blockIdx.x * blockDim.x + threadIdx.x;
    const size_t tot = (size_t)NT * HD / 4;
    if (i >= tot) return;
    int t = (int)(i / (HD/4));
    int r = (int)(i % (HD/4));
    float w0 = g_pw[2*t], w1v = g_pw[2*t+1];
    const float4* y2v = reinterpret_cast<const float4*>(g_y2);
    float4 a = y2v[(size_t)(2*t)   * (HD/4) + r];
    float4 b = y2v[(size_t)(2*t+1) * (HD/4) + r];
    float4 o;
    o.x = w0*a.x + w1v*b.x;
    o.y = w0*a.y + w1v*b.y;
    o.z = w0*a.z + w1v*b.z;
    o.w = w0*a.w + w1v*b.w;
    reinterpret_cast<float4*>(out)[i] = o;
}

// ============================================================
extern "C" void kernel_launch(void* const* d_in, const int* in_sizes, int n_in,
                              void* d_out, int out_size)
{
    const float* x  = (const float*)d_in[0];
    const float* rw = (const float*)d_in[1];
    const float* w1 = (const float*)d_in[2];
    const float* w2 = (const float*)d_in[3];
    float* out = (float*)d_out;

    cudaFuncSetAttribute(gemm1_tc, cudaFuncAttributeMaxDynamicSharedMemorySize, SMEM_BYTES);
    cudaFuncSetAttribute(gemm2_tc, cudaFuncAttributeMaxDynamicSharedMemorySize, SMEM_BYTES);

    router_kernel<<<NT/8, 256>>>(x, rw);
    assign_kernel<<<NP/256, 256>>>();
    gemm1_tc<<<dim3(ID/64,  NP/128, NE), 256, SMEM_BYTES>>>(x, w1);
    gemm2_tc<<<dim3(HD/128, NP/128, NE), 256, SMEM_BYTES>>>(w2);
    combine_kernel<<<(unsigned)(((size_t)NT*HD/4 + 255)/256), 256>>>(out);
}

// round 4
// speedup vs baseline: 3.3397x; 1.7778x over previous
#include <cuda_runtime.h>
#include <cuda_bf16.h>
#include <math.h>
#include <cstdint>

#define HD 2048
#define ID 1408
#define NE 8
#define NT 8192
#define NP (NT*2)

#define G1_BX 22   // ID/64 n-tiles for GEMM1 (128 weight rows = 64 act cols each)
#define G1_NC 64   // HD/32 k-chunks
#define G2_BX 16   // HD/128 n-tiles for GEMM2
#define G2_NC 44   // ID/32 k-chunks

// ---- scratch (device globals) ----
__device__ int   g_cnt[NE];
__device__ int   g_list[NE * NP];
__device__ int   g_eid[NP];
__device__ float g_pw[NP];
__device__ float g_act[(size_t)NP * ID];                       // ~92 MB (tf32-rounded)
__device__ float g_y2 [(size_t)NP * HD];                       // ~134 MB
__device__ float g_w1f[(size_t)NE * G1_BX * G1_NC * 4096];     // ~184 MB fragment-order tf32
__device__ float g_w2f[(size_t)NE * G2_BX * G2_NC * 4096];     // ~92 MB

__device__ __forceinline__ uint32_t tf32r(float f) {
    uint32_t r;
    asm("cvt.rna.tf32.f32 %0, %1;" : "=r"(r) : "f"(f));
    return r;
}

// m16n8k8 tf32 mma, fp32 accumulate
__device__ __forceinline__ void mma8(float* d, const uint32_t a0, const uint32_t a1,
                                     const uint32_t a2, const uint32_t a3,
                                     const uint32_t b0, const uint32_t b1) {
    asm volatile("mma.sync.aligned.m16n8k8.row.col.f32.tf32.tf32.f32 "
        "{%0,%1,%2,%3}, {%4,%5,%6,%7}, {%8,%9}, {%0,%1,%2,%3};"
        : "+f"(d[0]), "+f"(d[1]), "+f"(d[2]), "+f"(d[3])
        : "r"(a0), "r"(a1), "r"(a2), "r"(a3), "r"(b0), "r"(b1));
}

__device__ __forceinline__ void cpa16(uint32_t saddr, const float* gp) {
    asm volatile("cp.async.cg.shared.global [%0], [%1], 16;"
                 :: "r"(saddr), "l"(__cvta_generic_to_global(gp)) : "memory");
}
#define CP_COMMIT() asm volatile("cp.async.commit_group;" ::: "memory")
#define CP_WAIT1()  asm volatile("cp.async.wait_group 1;" ::: "memory")
#define CP_WAIT0()  asm volatile("cp.async.wait_group 0;" ::: "memory")

// SMEM: sp[128] @0, A bufs @512 (2x16KB), B bufs @33280 (2x16KB)
#define SM_SP   0
#define SM_A(b) (512 + (b) * 16384)
#define SM_B(b) (33280 + (b) * 16384)
#define SMEM_BYTES 66048

// A fragment layout (per m16/k8 tile of 128 words, XOR bank swizzle):
//   g = (m&7)*4 + ((k&3) ^ (m&3) ^ kt);  word = tile*128 + g*4 + ((k&7)>>2)*2 + ((m&15)>>3)
__device__ __forceinline__ void stageA2(uint32_t* AS, int m, int f, uint4 v) {
    int kt = f >> 1, kh = f & 1;
    int tilebase = (((m >> 4) * 4) + kt) * 128;
    int mh = (m >> 3) & 1;
    int gb = (m & 7) * 4;
    int x2 = (m & 3) ^ kt;
    uint32_t vv[4] = {v.x, v.y, v.z, v.w};
#pragma unroll
    for (int k3 = 0; k3 < 4; k3++)
        AS[tilebase + (gb + (k3 ^ x2)) * 4 + kh * 2 + mh] = vv[k3];
}

// ============================================================
// Weight preprocessing: tf32-round + fragment-order tiling
// B fragment layout per chunk: word = (nt*4+kt)*64 + (n&7)*8 + (k&3)*2 + ((k&7)>>2)
// ============================================================
__global__ __launch_bounds__(256) void prep_w1(const float* __restrict__ w1)
{
    int c = blockIdx.x, bx = blockIdx.y, e = blockIdx.z;
    const float* w1e = w1 + (size_t)e * 2 * ID * HD;
    float* dst = g_w1f + (((size_t)e * G1_BX + bx) * G1_NC + c) * 4096;
    int tid = threadIdx.x;
#pragma unroll
    for (int s = 0; s < 2; s++) {
        int g = tid * 2 + s;
        int n8 = g & 7, kt = (g >> 3) & 3, nt = g >> 5;
        int wrow = (nt & 1) * ID + bx * 64 + (nt >> 1) * 8 + n8;
        int k0 = c * 32 + kt * 8;
        const float* src = w1e + (size_t)wrow * HD + k0;
        float* d = dst + g * 8;
#pragma unroll
        for (int kk = 0; kk < 8; kk++)
            d[(kk & 3) * 2 + (kk >> 2)] = __uint_as_float(tf32r(src[kk]));
    }
}

__global__ __launch_bounds__(256) void prep_w2(const float* __restrict__ w2)
{
    int c = blockIdx.x, bx = blockIdx.y, e = blockIdx.z;
    const float* w2e = w2 + (size_t)e * HD * ID;
    float* dst = g_w2f + (((size_t)e * G2_BX + bx) * G2_NC + c) * 4096;
    int tid = threadIdx.x;
#pragma unroll
    for (int s = 0; s < 2; s++) {
        int g = tid * 2 + s;
        int n8 = g & 7, kt = (g >> 3) & 3, nt = g >> 5;
        int wrow = bx * 128 + nt * 8 + n8;
        int k0 = c * 32 + kt * 8;
        const float* src = w2e + (size_t)wrow * ID + k0;
        float* d = dst + g * 8;
#pragma unroll
        for (int kk = 0; kk < 8; kk++)
            d[(kk & 3) * 2 + (kk >> 2)] = __uint_as_float(tf32r(src[kk]));
    }
}

// ============================================================
// Kernel: router
// ============================================================
__global__ __launch_bounds__(256) void router_kernel(
    const float* __restrict__ x, const float* __restrict__ rw)
{
    int tid = threadIdx.x;
    if (blockIdx.x == 0 && tid < NE) g_cnt[tid] = 0;

    int warp = tid >> 5, lane = tid & 31;
    int t = blockIdx.x * 8 + warp;
    if (t >= NT) return;

    const float* xt = x + (size_t)t * HD;
    float acc[NE];
#pragma unroll
    for (int e = 0; e < NE; e++) acc[e] = 0.f;
    for (int h = lane; h < HD; h += 32) {
        float xv = xt[h];
#pragma unroll
        for (int e = 0; e < NE; e++) acc[e] += xv * __ldg(rw + e * HD + h);
    }
#pragma unroll
    for (int off = 16; off; off >>= 1)
#pragma unroll
        for (int e = 0; e < NE; e++) acc[e] += __shfl_xor_sync(0xffffffffu, acc[e], off);
    if (lane == 0) {
        int i0 = 0; float v0 = acc[0];
#pragma unroll
        for (int e = 1; e < NE; e++) if (acc[e] > v0) { v0 = acc[e]; i0 = e; }
        int i1 = -1; float v1 = -1e30f;
#pragma unroll
        for (int e = 0; e < NE; e++) if (e != i0 && acc[e] > v1) { v1 = acc[e]; i1 = e; }
        float w0 = 1.f / (1.f + expf(v1 - v0));
        g_eid[2*t] = i0; g_eid[2*t+1] = i1;
        g_pw[2*t] = w0;  g_pw[2*t+1] = 1.f - w0;
    }
}

__global__ __launch_bounds__(256) void assign_kernel()
{
    int p = blockIdx.x * blockDim.x + threadIdx.x;
    if (p < NP) {
        int e = g_eid[p];
        int pos = atomicAdd(&g_cnt[e], 1);
        g_list[e * NP + pos] = p;
    }
}

// ============================================================
// GEMM1: gathered A (x) x preprocessed w1 (gate/up interleaved) + SwiGLU
// ============================================================
__global__ __launch_bounds__(256, 2) void gemm1_tc(const float* __restrict__ x)
{
    const int e = blockIdx.z;
    const int cnt = g_cnt[e];
    const int m0 = blockIdx.y * 128;
    if (m0 >= cnt) return;
    const int bx = blockIdx.x;
    const int n0a = bx * 64;

    extern __shared__ char smem[];
    int* sp = (int*)(smem + SM_SP);

    const int tid = threadIdx.x;
    const int w = tid >> 5, lane = tid & 31;

    if (tid < 128) { int m = m0 + tid; sp[tid] = (m < cnt) ? g_list[e * NP + m] : -1; }
    __syncthreads();

    const int rgrp = tid >> 3;
    const int f = tid & 7;
    const float* arow[4];
#pragma unroll
    for (int j = 0; j < 4; j++) {
        int pa = sp[rgrp + 32 * j];
        arow[j] = (pa >= 0 ? x + (size_t)(pa >> 1) * HD : x) + f * 4;
    }
    const float* wsrc = g_w1f + (((size_t)e * G1_BX + bx) * G1_NC) * 4096;
    const uint32_t bdst0 = (uint32_t)__cvta_generic_to_shared(smem + SM_B(0));
    const uint32_t bdst1 = (uint32_t)__cvta_generic_to_shared(smem + SM_B(1));

    float acc[2][8][4];
#pragma unroll
    for (int i = 0; i < 2; i++)
#pragma unroll
        for (int n = 0; n < 8; n++)
#pragma unroll
            for (int c2 = 0; c2 < 4; c2++) acc[i][n][c2] = 0.f;

    float4 va[4];
    // ---- prologue: chunks 0,1 ----
#pragma unroll
    for (int j = 0; j < 4; j++) va[j] = *(const float4*)(arow[j]);
#pragma unroll
    for (int i = 0; i < 4; i++) cpa16(bdst0 + tid * 16 + i * 4096, wsrc + tid * 4 + i * 1024);
    CP_COMMIT();
    {
        uint32_t* AS = (uint32_t*)(smem + SM_A(0));
#pragma unroll
        for (int j = 0; j < 4; j++)
            stageA2(AS, rgrp + 32*j, f, make_uint4(tf32r(va[j].x), tf32r(va[j].y), tf32r(va[j].z), tf32r(va[j].w)));
    }
#pragma unroll
    for (int j = 0; j < 4; j++) va[j] = *(const float4*)(arow[j] + 32);
#pragma unroll
    for (int i = 0; i < 4; i++) cpa16(bdst1 + tid * 16 + i * 4096, wsrc + 4096 + tid * 4 + i * 1024);
    CP_COMMIT();
    {
        uint32_t* AS = (uint32_t*)(smem + SM_A(1));
#pragma unroll
        for (int j = 0; j < 4; j++)
            stageA2(AS, rgrp + 32*j, f, make_uint4(tf32r(va[j].x), tf32r(va[j].y), tf32r(va[j].z), tf32r(va[j].w)));
    }
#pragma unroll
    for (int j = 0; j < 4; j++) va[j] = *(const float4*)(arow[j] + 64);
    CP_WAIT1();
    __syncthreads();

    const int mtg0 = (w >> 1) * 2;
    const int bnt0 = (w & 1) * 8;
    const int laneg = lane ^ ((lane >> 2) & 3);

    const int NC = G1_NC;
    for (int c = 0; c < NC; c++) {
        {
            const uint32_t* AS = (const uint32_t*)(smem + SM_A(c & 1));
            const uint32_t* BS = (const uint32_t*)(smem + SM_B(c & 1));
#pragma unroll
            for (int kt = 0; kt < 4; kt++) {
                int ga = (laneg ^ kt) * 4;
                uint4 a0 = *(const uint4*)(AS + ((mtg0 + 0) * 4 + kt) * 128 + ga);
                uint4 a1 = *(const uint4*)(AS + ((mtg0 + 1) * 4 + kt) * 128 + ga);
#pragma unroll
                for (int n = 0; n < 8; n++) {
                    uint2 bb = *(const uint2*)(BS + ((bnt0 + n) * 4 + kt) * 64 + lane * 2);
                    mma8(acc[0][n], a0.x, a0.y, a0.z, a0.w, bb.x, bb.y);
                    mma8(acc[1][n], a1.x, a1.y, a1.z, a1.w, bb.x, bb.y);
                }
            }
        }
        __syncthreads();
        if (c + 2 < NC) {
            uint32_t* AS = (uint32_t*)(smem + SM_A(c & 1));
#pragma unroll
            for (int j = 0; j < 4; j++)
                stageA2(AS, rgrp + 32*j, f, make_uint4(tf32r(va[j].x), tf32r(va[j].y), tf32r(va[j].z), tf32r(va[j].w)));
            uint32_t bd = (c & 1) ? bdst1 : bdst0;
            const float* src = wsrc + (size_t)(c + 2) * 4096;
#pragma unroll
            for (int i = 0; i < 4; i++) cpa16(bd + tid * 16 + i * 4096, src + tid * 4 + i * 1024);
            CP_COMMIT();
            if (c + 3 < NC) {
                int k = (c + 3) * 32;
#pragma unroll
                for (int j = 0; j < 4; j++) va[j] = *(const float4*)(arow[j] + k);
            }
            CP_WAIT1();
            __syncthreads();
        } else if (c + 1 < NC) {
            CP_WAIT0();
            __syncthreads();
        }
    }

    // epilogue: interleaved gate/up n8 tiles -> silu(gate)*up, tf32-rounded to g_act
    const int gid = lane >> 2, ctg = lane & 3;
#pragma unroll
    for (int mt = 0; mt < 2; mt++) {
        int r0 = (w >> 1) * 32 + mt * 16 + gid;
        int p0 = sp[r0];
        int p1 = sp[r0 + 8];
#pragma unroll
        for (int pi = 0; pi < 4; pi++) {
            float* g = acc[mt][2 * pi];
            float* u = acc[mt][2 * pi + 1];
            int col = n0a + ((w & 1) * 4 + pi) * 8 + 2 * ctg;
            if (p0 >= 0) {
                float h0 = u[0] * g[0] / (1.f + expf(-g[0]));
                float h1 = u[1] * g[1] / (1.f + expf(-g[1]));
                *(float2*)(g_act + (size_t)p0 * ID + col) =
                    make_float2(__uint_as_float(tf32r(h0)), __uint_as_float(tf32r(h1)));
            }
            if (p1 >= 0) {
                float h2 = u[2] * g[2] / (1.f + expf(-g[2]));
                float h3 = u[3] * g[3] / (1.f + expf(-g[3]));
                *(float2*)(g_act + (size_t)p1 * ID + col) =
                    make_float2(__uint_as_float(tf32r(h2)), __uint_as_float(tf32r(h3)));
            }
        }
    }
}

// ============================================================
// GEMM2: gathered A (g_act, pre-rounded) x preprocessed w2
// ============================================================
__global__ __launch_bounds__(256, 2) void gemm2_tc()
{
    const int e = blockIdx.z;
    const int cnt = g_cnt[e];
    const int m0 = blockIdx.y * 128;
    if (m0 >= cnt) return;
    const int bx = blockIdx.x;
    const int n0 = bx * 128;

    extern __shared__ char smem[];
    int* sp = (int*)(smem + SM_SP);

    const int tid = threadIdx.x;
    const int w = tid >> 5, lane = tid & 31;

    if (tid < 128) { int m = m0 + tid; sp[tid] = (m < cnt) ? g_list[e * NP + m] : -1; }
    __syncthreads();

    const int rgrp = tid >> 3;
    const int f = tid & 7;
    const uint4* arow[4];
#pragma unroll
    for (int j = 0; j < 4; j++) {
        int pa = sp[rgrp + 32 * j];
        arow[j] = (const uint4*)((pa >= 0 ? g_act + (size_t)pa * ID : g_act) + f * 4);
    }
    const float* wsrc = g_w2f + (((size_t)e * G2_BX + bx) * G2_NC) * 4096;
    const uint32_t bdst0 = (uint32_t)__cvta_generic_to_shared(smem + SM_B(0));
    const uint32_t bdst1 = (uint32_t)__cvta_generic_to_shared(smem + SM_B(1));

    float acc[2][8][4];
#pragma unroll
    for (int i = 0; i < 2; i++)
#pragma unroll
        for (int n = 0; n < 8; n++)
#pragma unroll
            for (int c2 = 0; c2 < 4; c2++) acc[i][n][c2] = 0.f;

    uint4 va[4];
#pragma unroll
    for (int j = 0; j < 4; j++) va[j] = arow[j][0];
#pragma unroll
    for (int i = 0; i < 4; i++) cpa16(bdst0 + tid * 16 + i * 4096, wsrc + tid * 4 + i * 1024);
    CP_COMMIT();
    {
        uint32_t* AS = (uint32_t*)(smem + SM_A(0));
#pragma unroll
        for (int j = 0; j < 4; j++) stageA2(AS, rgrp + 32*j, f, va[j]);
    }
#pragma unroll
    for (int j = 0; j < 4; j++) va[j] = arow[j][8];   // +32 floats = 8 uint4
#pragma unroll
    for (int i = 0; i < 4; i++) cpa16(bdst1 + tid * 16 + i * 4096, wsrc + 4096 + tid * 4 + i * 1024);
    CP_COMMIT();
    {
        uint32_t* AS = (uint32_t*)(smem + SM_A(1));
#pragma unroll
        for (int j = 0; j < 4; j++) stageA2(AS, rgrp + 32*j, f, va[j]);
    }
#pragma unroll
    for (int j = 0; j < 4; j++) va[j] = arow[j][16];
    CP_WAIT1();
    __syncthreads();

    const int mtg0 = (w >> 1) * 2;
    const int bnt0 = (w & 1) * 8;
    const int laneg = lane ^ ((lane >> 2) & 3);

    const int NC = G2_NC;
    for (int c = 0; c < NC; c++) {
        {
            const uint32_t* AS = (const uint32_t*)(smem + SM_A(c & 1));
            const uint32_t* BS = (const uint32_t*)(smem + SM_B(c & 1));
#pragma unroll
            for (int kt = 0; kt < 4; kt++) {
                int ga = (laneg ^ kt) * 4;
                uint4 a0 = *(const uint4*)(AS + ((mtg0 + 0) * 4 + kt) * 128 + ga);
                uint4 a1 = *(const uint4*)(AS + ((mtg0 + 1) * 4 + kt) * 128 + ga);
#pragma unroll
                for (int n = 0; n < 8; n++) {
                    uint2 bb = *(const uint2*)(BS + ((bnt0 + n) * 4 + kt) * 64 + lane * 2);
                    mma8(acc[0][n], a0.x, a0.y, a0.z, a0.w, bb.x, bb.y);
                    mma8(acc[1][n], a1.x, a1.y, a1.z, a1.w, bb.x, bb.y);
                }
            }
        }
        __syncthreads();
        if (c + 2 < NC) {
            uint32_t* AS = (uint32_t*)(smem + SM_A(c & 1));
#pragma unroll
            for (int j = 0; j < 4; j++) stageA2(AS, rgrp + 32*j, f, va[j]);
            uint32_t bd = (c & 1) ? bdst1 : bdst0;
            const float* src = wsrc + (size_t)(c + 2) * 4096;
#pragma unroll
            for (int i = 0; i < 4; i++) cpa16(bd + tid * 16 + i * 4096, src + tid * 4 + i * 1024);
            CP_COMMIT();
            if (c + 3 < NC) {
                int k8 = (c + 3) * 8;
#pragma unroll
                for (int j = 0; j < 4; j++) va[j] = arow[j][k8];
            }
            CP_WAIT1();
            __syncthreads();
        } else if (c + 1 < NC) {
            CP_WAIT0();
            __syncthreads();
        }
    }

    const int gid = lane >> 2, ctg = lane & 3;
#pragma unroll
    for (int mt = 0; mt < 2; mt++) {
        int r0 = (w >> 1) * 32 + mt * 16 + gid;
        int p0 = sp[r0];
        int p1 = sp[r0 + 8];
#pragma unroll
        for (int n = 0; n < 8; n++) {
            int col = n0 + ((w & 1) * 8 + n) * 8 + 2 * ctg;
            if (p0 >= 0)
                *(float2*)(g_y2 + (size_t)p0 * HD + col) = make_float2(acc[mt][n][0], acc[mt][n][1]);
            if (p1 >= 0)
                *(float2*)(g_y2 + (size_t)p1 * HD + col) = make_float2(acc[mt][n][2], acc[mt][n][3]);
        }
    }
}

// ============================================================
// Kernel: combine
// ============================================================
__global__ __launch_bounds__(256) void combine_kernel(float* __restrict__ out)
{
    size_t i = (size_t)blockIdx.x * blockDim.x + threadIdx.x;
    const size_t tot = (size_t)NT * HD / 4;
    if (i >= tot) return;
    int t = (int)(i / (HD/4));
    int r = (int)(i % (HD/4));
    float w0 = g_pw[2*t], w1v = g_pw[2*t+1];
    const float4* y2v = reinterpret_cast<const float4*>(g_y2);
    float4 a = y2v[(size_t)(2*t)   * (HD/4) + r];
    float4 b = y2v[(size_t)(2*t+1) * (HD/4) + r];
    float4 o;
    o.x = w0*a.x + w1v*b.x;
    o.y = w0*a.y + w1v*b.y;
    o.z = w0*a.z + w1v*b.z;
    o.w = w0*a.w + w1v*b.w;
    reinterpret_cast<float4*>(out)[i] = o;
}

// ============================================================
extern "C" void kernel_launch(void* const* d_in, const int* in_sizes, int n_in,
                              void* d_out, int out_size)
{
    const float* x  = (const float*)d_in[0];
    const float* rw = (const float*)d_in[1];
    const float* w1 = (const float*)d_in[2];
    const float* w2 = (const float*)d_in[3];
    float* out = (float*)d_out;

    cudaFuncSetAttribute(gemm1_tc, cudaFuncAttributeMaxDynamicSharedMemorySize, SMEM_BYTES);
    cudaFuncSetAttribute(gemm2_tc, cudaFuncAttributeMaxDynamicSharedMemorySize, SMEM_BYTES);

    prep_w1<<<dim3(G1_NC, G1_BX, NE), 256>>>(w1);
    prep_w2<<<dim3(G2_NC, G2_BX, NE), 256>>>(w2);
    router_kernel<<<NT/8, 256>>>(x, rw);
    assign_kernel<<<NP/256, 256>>>();
    gemm1_tc<<<dim3(G1_BX, NP/128, NE), 256, SMEM_BYTES>>>(x);
    gemm2_tc<<<dim3(G2_BX, NP/128, NE), 256, SMEM_BYTES>>>();
    combine_kernel<<<(unsigned)(((size_t)NT*HD/4 + 255)/256), 256>>>(out);
}

// round 5
// speedup vs baseline: 5.3515x; 1.6024x over previous
#include <cuda_runtime.h>
#include <cuda_fp16.h>
#include <math.h>
#include <cstdint>

#define HD 2048
#define ID 1408
#define NE 8
#define NT 8192
#define NP (NT*2)

#define G1_BX 22   // ID/64 n-tiles (GEMM1: 128 weight rows = 64 act cols)
#define G1_NC 64   // HD/32 k-chunks
#define G2_BX 16   // HD/128 n-tiles (GEMM2)
#define G2_NC 44   // ID/32 k-chunks

// ---- scratch (device globals) ----
__device__ int   g_cnt[NE];
__device__ int   g_list[NE * NP];
__device__ int   g_eid[NP];
__device__ float g_pw[NP];
__device__ __align__(16) __half g_xh [(size_t)NT * HD];                    // 33 MB
__device__ __align__(16) __half g_act[(size_t)NP * ID];                    // 46 MB
__device__ float g_y2 [(size_t)NP * HD];                                   // 134 MB
__device__ __align__(16) __half g_w1h[(size_t)NE * G1_BX * G1_NC * 4096];  // 92 MB tiled
__device__ __align__(16) __half g_w2h[(size_t)NE * G2_BX * G2_NC * 4096];  // 46 MB tiled

// fp16 mma m16n8k16, fp32 accumulate
__device__ __forceinline__ void mma16(float* d, uint32_t a0, uint32_t a1, uint32_t a2, uint32_t a3,
                                      uint32_t b0, uint32_t b1) {
    asm volatile("mma.sync.aligned.m16n8k16.row.col.f32.f16.f16.f32 "
        "{%0,%1,%2,%3}, {%4,%5,%6,%7}, {%8,%9}, {%0,%1,%2,%3};"
        : "+f"(d[0]), "+f"(d[1]), "+f"(d[2]), "+f"(d[3])
        : "r"(a0), "r"(a1), "r"(a2), "r"(a3), "r"(b0), "r"(b1));
}

__device__ __forceinline__ void ldsm4(uint32_t* r, uint32_t addr) {
    asm volatile("ldmatrix.sync.aligned.m8n8.x4.shared.b16 {%0,%1,%2,%3}, [%4];"
        : "=r"(r[0]), "=r"(r[1]), "=r"(r[2]), "=r"(r[3]) : "r"(addr));
}

__device__ __forceinline__ void cpa16(uint32_t saddr, const void* gp) {
    asm volatile("cp.async.cg.shared.global [%0], [%1], 16;"
                 :: "r"(saddr), "l"(__cvta_generic_to_global(gp)) : "memory");
}
#define CP_COMMIT() asm volatile("cp.async.commit_group;" ::: "memory")
#define CP_WAIT2()  asm volatile("cp.async.wait_group 2;" ::: "memory")
#define CP_WAIT0()  asm volatile("cp.async.wait_group 0;" ::: "memory")

// SMEM: sp[128] @0; A stages @512 (4 x 8KB); B stages @33280 (4 x 8KB)
#define SM_SP   0
#define SM_A(s) (512 + (s) * 8192)
#define SM_B(s) (33280 + (s) * 8192)
#define SMEM_BYTES 66048
#define NSTG 4

// Chunk layouts (both A and B): 16 blocks of 512B; block = 4 mats x (8 rows x 16B).
// A block (mt,kt16): mats = (mlo,klo8),(mhi,klo8),(mlo,khi8),(mhi,khi8)
// B block (ntp,kt16): mats = (nt0,klo8),(nt0,khi8),(nt1,klo8),(nt1,khi8)

// ============================================================
// prep_x: fp32 -> fp16
// ============================================================
__global__ __launch_bounds__(256) void prep_x(const float* __restrict__ x)
{
    size_t i = (size_t)blockIdx.x * 256 + threadIdx.x;
    float4 v = reinterpret_cast<const float4*>(x)[i];
    __half2 h0 = __floats2half2_rn(v.x, v.y);
    __half2 h1 = __floats2half2_rn(v.z, v.w);
    uint2 o;
    o.x = *(uint32_t*)&h0;
    o.y = *(uint32_t*)&h1;
    reinterpret_cast<uint2*>(g_xh)[i] = o;
}

// ============================================================
// prep_w1 / prep_w2: fp32 -> fp16, ldmatrix tile order
// ============================================================
__global__ __launch_bounds__(256) void prep_w1(const float* __restrict__ w1)
{
    int c = blockIdx.x, bx = blockIdx.y, e = blockIdx.z;
    const float* w1e = w1 + (size_t)e * 2 * ID * HD;
    __half* dst = g_w1h + (((size_t)e * G1_BX + bx) * G1_NC + c) * 4096;
    int tid = threadIdx.x;
#pragma unroll
    for (int s = 0; s < 2; s++) {
        int piece = tid * 2 + s;            // = blk*32 + mat*8 + row
        int row = piece & 7;
        int mat = (piece >> 3) & 3;
        int blk = piece >> 5;               // ntp*2 + kt
        int kt = blk & 1, ntp = blk >> 1;
        int nt = ntp * 2 + (mat >> 1);
        int kh8 = mat & 1;
        int wrow = (nt & 1) * ID + bx * 64 + (nt >> 1) * 8 + row;
        int k = c * 32 + kt * 16 + kh8 * 8;
        const float* src = w1e + (size_t)wrow * HD + k;
        __half hv[8];
#pragma unroll
        for (int kk = 0; kk < 8; kk++) hv[kk] = __float2half_rn(src[kk]);
        *(uint4*)(dst + piece * 8) = *(uint4*)hv;
    }
}

__global__ __launch_bounds__(256) void prep_w2(const float* __restrict__ w2)
{
    int c = blockIdx.x, bx = blockIdx.y, e = blockIdx.z;
    const float* w2e = w2 + (size_t)e * HD * ID;
    __half* dst = g_w2h + (((size_t)e * G2_BX + bx) * G2_NC + c) * 4096;
    int tid = threadIdx.x;
#pragma unroll
    for (int s = 0; s < 2; s++) {
        int piece = tid * 2 + s;
        int row = piece & 7;
        int mat = (piece >> 3) & 3;
        int blk = piece >> 5;
        int kt = blk & 1, ntp = blk >> 1;
        int nt = ntp * 2 + (mat >> 1);
        int kh8 = mat & 1;
        int wrow = bx * 128 + nt * 8 + row;
        int k = c * 32 + kt * 16 + kh8 * 8;
        const float* src = w2e + (size_t)wrow * ID + k;
        __half hv[8];
#pragma unroll
        for (int kk = 0; kk < 8; kk++) hv[kk] = __float2half_rn(src[kk]);
        *(uint4*)(dst + piece * 8) = *(uint4*)hv;
    }
}

// ============================================================
// router
// ============================================================
__global__ __launch_bounds__(256) void router_kernel(
    const float* __restrict__ x, const float* __restrict__ rw)
{
    int tid = threadIdx.x;
    if (blockIdx.x == 0 && tid < NE) g_cnt[tid] = 0;

    int warp = tid >> 5, lane = tid & 31;
    int t = blockIdx.x * 8 + warp;
    if (t >= NT) return;

    const float* xt = x + (size_t)t * HD;
    float acc[NE];
#pragma unroll
    for (int e = 0; e < NE; e++) acc[e] = 0.f;
    for (int h = lane; h < HD; h += 32) {
        float xv = xt[h];
#pragma unroll
        for (int e = 0; e < NE; e++) acc[e] += xv * __ldg(rw + e * HD + h);
    }
#pragma unroll
    for (int off = 16; off; off >>= 1)
#pragma unroll
        for (int e = 0; e < NE; e++) acc[e] += __shfl_xor_sync(0xffffffffu, acc[e], off);
    if (lane == 0) {
        int i0 = 0; float v0 = acc[0];
#pragma unroll
        for (int e = 1; e < NE; e++) if (acc[e] > v0) { v0 = acc[e]; i0 = e; }
        int i1 = -1; float v1 = -1e30f;
#pragma unroll
        for (int e = 0; e < NE; e++) if (e != i0 && acc[e] > v1) { v1 = acc[e]; i1 = e; }
        float w0 = 1.f / (1.f + expf(v1 - v0));
        g_eid[2*t] = i0; g_eid[2*t+1] = i1;
        g_pw[2*t] = w0;  g_pw[2*t+1] = 1.f - w0;
    }
}

__global__ __launch_bounds__(256) void assign_kernel()
{
    int p = blockIdx.x * blockDim.x + threadIdx.x;
    if (p < NP) {
        int e = g_eid[p];
        int pos = atomicAdd(&g_cnt[e], 1);
        g_list[e * NP + pos] = p;
    }
}

// ============================================================
// GEMM1: gathered xh (fp16) x tiled w1h + SwiGLU -> g_act (fp16)
// ============================================================
__global__ __launch_bounds__(256, 2) void gemm1_tc()
{
    const int e = blockIdx.z;
    const int cnt = g_cnt[e];
    const int m0 = blockIdx.y * 128;
    if (m0 >= cnt) return;
    const int bx = blockIdx.x;
    const int n0a = bx * 64;

    extern __shared__ char smem[];
    int* sp = (int*)(smem + SM_SP);
    const uint32_t sb = (uint32_t)__cvta_generic_to_shared(smem);

    const int tid = threadIdx.x;
    const int w = tid >> 5, lane = tid & 31;

    if (tid < 128) { int m = m0 + tid; sp[tid] = (m < cnt) ? g_list[e * NP + m] : -1; }
    __syncthreads();

    // A loader mapping: thread handles row m_row, two 16B pieces (k8 groups)
    const int m_row = tid >> 1;
    const int pa = sp[m_row];
    const __half* asrc = g_xh + (size_t)(pa >= 0 ? (pa >> 1) : 0) * HD;
    const int mt = m_row >> 4, row = m_row & 7, mh = (m_row >> 3) & 1;
    uint32_t dstA[2]; int srcA[2];
#pragma unroll
    for (int s = 0; s < 2; s++) {
        int g8 = (tid & 1) * 2 + s;
        int kt = g8 >> 1, kh8 = g8 & 1;
        int mat = mh + 2 * kh8;
        dstA[s] = (uint32_t)((mt * 2 + kt) * 512 + mat * 128 + row * 16);
        srcA[s] = g8 * 8;
    }
    const __half* wsrc = g_w1h + (((size_t)e * G1_BX + bx) * G1_NC) * 4096;

    float acc[2][8][4];
#pragma unroll
    for (int i = 0; i < 2; i++)
#pragma unroll
        for (int n = 0; n < 8; n++)
#pragma unroll
            for (int c2 = 0; c2 < 4; c2++) acc[i][n][c2] = 0.f;

    // prologue: issue chunks 0..2
#pragma unroll
    for (int pc = 0; pc < 3; pc++) {
        uint32_t ab = sb + SM_A(pc), bb = sb + SM_B(pc);
#pragma unroll
        for (int s = 0; s < 2; s++) {
            cpa16(ab + dstA[s], asrc + pc * 32 + srcA[s]);
            cpa16(bb + tid * 32 + s * 16, wsrc + (size_t)pc * 4096 + tid * 16 + s * 8);
        }
        CP_COMMIT();
    }

    const int mtg0 = (w >> 1) * 2;
    const int ntp0 = (w & 1) * 4;
    const uint32_t loff = (uint32_t)((lane >> 3) * 128 + (lane & 7) * 16);

    const int NC = G1_NC;
    for (int c = 0; c < NC; c++) {
        CP_WAIT2();
        __syncthreads();
        const int st = c & (NSTG - 1);
        const uint32_t ab = sb + SM_A(st), bb = sb + SM_B(st);
#pragma unroll
        for (int kt = 0; kt < 2; kt++) {
            uint32_t A0[4], A1[4];
            ldsm4(A0, ab + (uint32_t)(((mtg0 + 0) * 2 + kt) * 512) + loff);
            ldsm4(A1, ab + (uint32_t)(((mtg0 + 1) * 2 + kt) * 512) + loff);
#pragma unroll
            for (int j = 0; j < 4; j++) {
                uint32_t B[4];
                ldsm4(B, bb + (uint32_t)(((ntp0 + j) * 2 + kt) * 512) + loff);
                mma16(acc[0][2*j],   A0[0], A0[1], A0[2], A0[3], B[0], B[1]);
                mma16(acc[1][2*j],   A1[0], A1[1], A1[2], A1[3], B[0], B[1]);
                mma16(acc[0][2*j+1], A0[0], A0[1], A0[2], A0[3], B[2], B[3]);
                mma16(acc[1][2*j+1], A1[0], A1[1], A1[2], A1[3], B[2], B[3]);
            }
        }
        __syncthreads();
        if (c + 3 < NC) {
            const int nc2 = c + 3;
            const int st2 = nc2 & (NSTG - 1);
            uint32_t ab2 = sb + SM_A(st2), bb2 = sb + SM_B(st2);
#pragma unroll
            for (int s = 0; s < 2; s++) {
                cpa16(ab2 + dstA[s], asrc + nc2 * 32 + srcA[s]);
                cpa16(bb2 + tid * 32 + s * 16, wsrc + (size_t)nc2 * 4096 + tid * 16 + s * 8);
            }
        }
        CP_COMMIT();
    }

    // epilogue: nt even = gate, odd = up -> silu(gate)*up, fp16 out
    const int gid = lane >> 2, ctg = lane & 3;
#pragma unroll
    for (int mt2 = 0; mt2 < 2; mt2++) {
        int r0 = (w >> 1) * 32 + mt2 * 16 + gid;
        int p0 = sp[r0];
        int p1 = sp[r0 + 8];
#pragma unroll
        for (int j = 0; j < 4; j++) {
            float* g = acc[mt2][2 * j];
            float* u = acc[mt2][2 * j + 1];
            int col = n0a + ((w & 1) * 4 + j) * 8 + 2 * ctg;
            if (p0 >= 0) {
                float h0 = u[0] * g[0] / (1.f + expf(-g[0]));
                float h1 = u[1] * g[1] / (1.f + expf(-g[1]));
                __half2 hv = __floats2half2_rn(h0, h1);
                *(__half2*)(g_act + (size_t)p0 * ID + col) = hv;
            }
            if (p1 >= 0) {
                float h2 = u[2] * g[2] / (1.f + expf(-g[2]));
                float h3 = u[3] * g[3] / (1.f + expf(-g[3]));
                __half2 hv = __floats2half2_rn(h2, h3);
                *(__half2*)(g_act + (size_t)p1 * ID + col) = hv;
            }
        }
    }
}

// ============================================================
// GEMM2: gathered g_act (fp16) x tiled w2h -> g_y2 (fp32)
// ============================================================
__global__ __launch_bounds__(256, 2) void gemm2_tc()
{
    const int e = blockIdx.z;
    const int cnt = g_cnt[e];
    const int m0 = blockIdx.y * 128;
    if (m0 >= cnt) return;
    const int bx = blockIdx.x;
    const int n0 = bx * 128;

    extern __shared__ char smem[];
    int* sp = (int*)(smem + SM_SP);
    const uint32_t sb = (uint32_t)__cvta_generic_to_shared(smem);

    const int tid = threadIdx.x;
    const int w = tid >> 5, lane = tid & 31;

    if (tid < 128) { int m = m0 + tid; sp[tid] = (m < cnt) ? g_list[e * NP + m] : -1; }
    __syncthreads();

    const int m_row = tid >> 1;
    const int pa = sp[m_row];
    const __half* asrc = g_act + (size_t)(pa >= 0 ? pa : 0) * ID;
    const int mt = m_row >> 4, row = m_row & 7, mh = (m_row >> 3) & 1;
    uint32_t dstA[2]; int srcA[2];
#pragma unroll
    for (int s = 0; s < 2; s++) {
        int g8 = (tid & 1) * 2 + s;
        int kt = g8 >> 1, kh8 = g8 & 1;
        int mat = mh + 2 * kh8;
        dstA[s] = (uint32_t)((mt * 2 + kt) * 512 + mat * 128 + row * 16);
        srcA[s] = g8 * 8;
    }
    const __half* wsrc = g_w2h + (((size_t)e * G2_BX + bx) * G2_NC) * 4096;

    float acc[2][8][4];
#pragma unroll
    for (int i = 0; i < 2; i++)
#pragma unroll
        for (int n = 0; n < 8; n++)
#pragma unroll
            for (int c2 = 0; c2 < 4; c2++) acc[i][n][c2] = 0.f;

#pragma unroll
    for (int pc = 0; pc < 3; pc++) {
        uint32_t ab = sb + SM_A(pc), bb = sb + SM_B(pc);
#pragma unroll
        for (int s = 0; s < 2; s++) {
            cpa16(ab + dstA[s], asrc + pc * 32 + srcA[s]);
            cpa16(bb + tid * 32 + s * 16, wsrc + (size_t)pc * 4096 + tid * 16 + s * 8);
        }
        CP_COMMIT();
    }

    const int mtg0 = (w >> 1) * 2;
    const int ntp0 = (w & 1) * 4;
    const uint32_t loff = (uint32_t)((lane >> 3) * 128 + (lane & 7) * 16);

    const int NC = G2_NC;
    for (int c = 0; c < NC; c++) {
        CP_WAIT2();
        __syncthreads();
        const int st = c & (NSTG - 1);
        const uint32_t ab = sb + SM_A(st), bb = sb + SM_B(st);
#pragma unroll
        for (int kt = 0; kt < 2; kt++) {
            uint32_t A0[4], A1[4];
            ldsm4(A0, ab + (uint32_t)(((mtg0 + 0) * 2 + kt) * 512) + loff);
            ldsm4(A1, ab + (uint32_t)(((mtg0 + 1) * 2 + kt) * 512) + loff);
#pragma unroll
            for (int j = 0; j < 4; j++) {
                uint32_t B[4];
                ldsm4(B, bb + (uint32_t)(((ntp0 + j) * 2 + kt) * 512) + loff);
                mma16(acc[0][2*j],   A0[0], A0[1], A0[2], A0[3], B[0], B[1]);
                mma16(acc[1][2*j],   A1[0], A1[1], A1[2], A1[3], B[0], B[1]);
                mma16(acc[0][2*j+1], A0[0], A0[1], A0[2], A0[3], B[2], B[3]);
                mma16(acc[1][2*j+1], A1[0], A1[1], A1[2], A1[3], B[2], B[3]);
            }
        }
        __syncthreads();
        if (c + 3 < NC) {
            const int nc2 = c + 3;
            const int st2 = nc2 & (NSTG - 1);
            uint32_t ab2 = sb + SM_A(st2), bb2 = sb + SM_B(st2);
#pragma unroll
            for (int s = 0; s < 2; s++) {
                cpa16(ab2 + dstA[s], asrc + nc2 * 32 + srcA[s]);
                cpa16(bb2 + tid * 32 + s * 16, wsrc + (size_t)nc2 * 4096 + tid * 16 + s * 8);
            }
        }
        CP_COMMIT();
    }

    const int gid = lane >> 2, ctg = lane & 3;
#pragma unroll
    for (int mt2 = 0; mt2 < 2; mt2++) {
        int r0 = (w >> 1) * 32 + mt2 * 16 + gid;
        int p0 = sp[r0];
        int p1 = sp[r0 + 8];
#pragma unroll
        for (int n = 0; n < 8; n++) {
            int col = n0 + ((w & 1) * 8 + n) * 8 + 2 * ctg;
            if (p0 >= 0)
                *(float2*)(g_y2 + (size_t)p0 * HD + col) = make_float2(acc[mt2][n][0], acc[mt2][n][1]);
            if (p1 >= 0)
                *(float2*)(g_y2 + (size_t)p1 * HD + col) = make_float2(acc[mt2][n][2], acc[mt2][n][3]);
        }
    }
}

// ============================================================
// combine
// ============================================================
__global__ __launch_bounds__(256) void combine_kernel(float* __restrict__ out)
{
    size_t i = (size_t)blockIdx.x * blockDim.x + threadIdx.x;
    const size_t tot = (size_t)NT * HD / 4;
    if (i >= tot) return;
    int t = (int)(i / (HD/4));
    int r = (int)(i % (HD/4));
    float w0 = g_pw[2*t], w1v = g_pw[2*t+1];
    const float4* y2v = reinterpret_cast<const float4*>(g_y2);
    float4 a = y2v[(size_t)(2*t)   * (HD/4) + r];
    float4 b = y2v[(size_t)(2*t+1) * (HD/4) + r];
    float4 o;
    o.x = w0*a.x + w1v*b.x;
    o.y = w0*a.y + w1v*b.y;
    o.z = w0*a.z + w1v*b.z;
    o.w = w0*a.w + w1v*b.w;
    reinterpret_cast<float4*>(out)[i] = o;
}

// ============================================================
extern "C" void kernel_launch(void* const* d_in, const int* in_sizes, int n_in,
                              void* d_out, int out_size)
{
    const float* x  = (const float*)d_in[0];
    const float* rw = (const float*)d_in[1];
    const float* w1 = (const float*)d_in[2];
    const float* w2 = (const float*)d_in[3];
    float* out = (float*)d_out;

    cudaFuncSetAttribute(gemm1_tc, cudaFuncAttributeMaxDynamicSharedMemorySize, SMEM_BYTES);
    cudaFuncSetAttribute(gemm2_tc, cudaFuncAttributeMaxDynamicSharedMemorySize, SMEM_BYTES);

    prep_x<<<NT * HD / 1024, 256>>>(x);
    prep_w1<<<dim3(G1_NC, G1_BX, NE), 256>>>(w1);
    prep_w2<<<dim3(G2_NC, G2_BX, NE), 256>>>(w2);
    router_kernel<<<NT/8, 256>>>(x, rw);
    assign_kernel<<<NP/256, 256>>>();
    gemm1_tc<<<dim3(G1_BX, NP/128, NE), 256, SMEM_BYTES>>>();
    gemm2_tc<<<dim3(G2_BX, NP/128, NE), 256, SMEM_BYTES>>>();
    combine_kernel<<<(unsigned)(((size_t)NT*HD/4 + 255)/256), 256>>>(out);
}

// round 6
// speedup vs baseline: 5.4070x; 1.0104x over previous
#include <cuda_runtime.h>
#include <cuda_fp16.h>
#include <math.h>
#include <cstdint>

#define HD 2048
#define ID 1408
#define NE 8
#define NT 8192
#define NP (NT*2)

#define G1_BX 22   // ID/64 n-tiles (GEMM1)
#define G1_NC 64   // HD/32 k-chunks
#define G2_BX 16   // HD/128 n-tiles (GEMM2)
#define G2_NC 44   // ID/32 k-chunks

// ---- scratch (device globals) ----
__device__ int   g_cnt[NE];
__device__ int   g_list[NE * NP];
__device__ float g_pw[NP];
__device__ __align__(16) __half g_xh [(size_t)NT * HD];                    // 33 MB
__device__ __align__(16) __half g_act[(size_t)NP * ID];                    // 46 MB
__device__ __align__(16) __half g_y2h[(size_t)NP * HD];                    // 67 MB
__device__ __align__(16) __half g_w1h[(size_t)NE * G1_BX * G1_NC * 4096];  // 92 MB tiled
__device__ __align__(16) __half g_w2h[(size_t)NE * G2_BX * G2_NC * 4096];  // 46 MB tiled

// fp16 mma m16n8k16, fp32 accumulate
__device__ __forceinline__ void mma16(float* d, uint32_t a0, uint32_t a1, uint32_t a2, uint32_t a3,
                                      uint32_t b0, uint32_t b1) {
    asm volatile("mma.sync.aligned.m16n8k16.row.col.f32.f16.f16.f32 "
        "{%0,%1,%2,%3}, {%4,%5,%6,%7}, {%8,%9}, {%0,%1,%2,%3};"
        : "+f"(d[0]), "+f"(d[1]), "+f"(d[2]), "+f"(d[3])
        : "r"(a0), "r"(a1), "r"(a2), "r"(a3), "r"(b0), "r"(b1));
}

__device__ __forceinline__ void ldsm4(uint32_t* r, uint32_t addr) {
    asm volatile("ldmatrix.sync.aligned.m8n8.x4.shared.b16 {%0,%1,%2,%3}, [%4];"
        : "=r"(r[0]), "=r"(r[1]), "=r"(r[2]), "=r"(r[3]) : "r"(addr));
}

__device__ __forceinline__ void cpa16(uint32_t saddr, const void* gp) {
    asm volatile("cp.async.cg.shared.global [%0], [%1], 16;"
                 :: "r"(saddr), "l"(__cvta_generic_to_global(gp)) : "memory");
}
#define CP_COMMIT() asm volatile("cp.async.commit_group;" ::: "memory")
#define CP_WAIT2()  asm volatile("cp.async.wait_group 2;" ::: "memory")

// SMEM: sp[128] @0; A stages @512 (4 x 8KB); B stages @33280 (4 x 8KB)
#define SM_SP   0
#define SM_A(s) (512 + (s) * 8192)
#define SM_B(s) (33280 + (s) * 8192)
#define SMEM_BYTES 66048
#define NSTG 4

// ============================================================
// prep_w1 / prep_w2: fp32 -> fp16, ldmatrix tile order
// ============================================================
__global__ __launch_bounds__(256) void prep_w1(const float* __restrict__ w1)
{
    int c = blockIdx.x, bx = blockIdx.y, e = blockIdx.z;
    if (c == 0 && bx == 0 && e == 0 && threadIdx.x < NE) g_cnt[threadIdx.x] = 0;
    const float* w1e = w1 + (size_t)e * 2 * ID * HD;
    __half* dst = g_w1h + (((size_t)e * G1_BX + bx) * G1_NC + c) * 4096;
    int tid = threadIdx.x;
#pragma unroll
    for (int s = 0; s < 2; s++) {
        int piece = tid * 2 + s;            // blk*32 + mat*8 + row
        int row = piece & 7;
        int mat = (piece >> 3) & 3;
        int blk = piece >> 5;               // ntp*2 + kt
        int kt = blk & 1, ntp = blk >> 1;
        int nt = ntp * 2 + (mat >> 1);
        int kh8 = mat & 1;
        int wrow = (nt & 1) * ID + bx * 64 + (nt >> 1) * 8 + row;
        int k = c * 32 + kt * 16 + kh8 * 8;
        const float* src = w1e + (size_t)wrow * HD + k;
        __half hv[8];
#pragma unroll
        for (int kk = 0; kk < 8; kk++) hv[kk] = __float2half_rn(src[kk]);
        *(uint4*)(dst + piece * 8) = *(uint4*)hv;
    }
}

__global__ __launch_bounds__(256) void prep_w2(const float* __restrict__ w2)
{
    int c = blockIdx.x, bx = blockIdx.y, e = blockIdx.z;
    const float* w2e = w2 + (size_t)e * HD * ID;
    __half* dst = g_w2h + (((size_t)e * G2_BX + bx) * G2_NC + c) * 4096;
    int tid = threadIdx.x;
#pragma unroll
    for (int s = 0; s < 2; s++) {
        int piece = tid * 2 + s;
        int row = piece & 7;
        int mat = (piece >> 3) & 3;
        int blk = piece >> 5;
        int kt = blk & 1, ntp = blk >> 1;
        int nt = ntp * 2 + (mat >> 1);
        int kh8 = mat & 1;
        int wrow = bx * 128 + nt * 8 + row;
        int k = c * 32 + kt * 16 + kh8 * 8;
        const float* src = w2e + (size_t)wrow * ID + k;
        __half hv[8];
#pragma unroll
        for (int kk = 0; kk < 8; kk++) hv[kk] = __float2half_rn(src[kk]);
        *(uint4*)(dst + piece * 8) = *(uint4*)hv;
    }
}

// ============================================================
// router: logits (fp32, float4) + top-2 softmax + inline scatter + x->fp16
// One warp per token.
// ============================================================
__global__ __launch_bounds__(256) void router_kernel(
    const float* __restrict__ x, const float* __restrict__ rw)
{
    int tid = threadIdx.x;
    int warp = tid >> 5, lane = tid & 31;
    int t = blockIdx.x * 8 + warp;

    const float4* xt = reinterpret_cast<const float4*>(x + (size_t)t * HD);
    const float4* rwv = reinterpret_cast<const float4*>(rw);
    uint2* xh = reinterpret_cast<uint2*>(g_xh + (size_t)t * HD);

    float acc[NE];
#pragma unroll
    for (int e = 0; e < NE; e++) acc[e] = 0.f;

#pragma unroll
    for (int i = 0; i < 16; i++) {
        int idx = lane + i * 32;
        float4 xv = xt[idx];
        // write fp16 copy of x
        __half2 h0 = __floats2half2_rn(xv.x, xv.y);
        __half2 h1 = __floats2half2_rn(xv.z, xv.w);
        uint2 o; o.x = *(uint32_t*)&h0; o.y = *(uint32_t*)&h1;
        xh[idx] = o;
#pragma unroll
        for (int e = 0; e < NE; e++) {
            float4 wv = __ldg(rwv + e * (HD/4) + idx);
            acc[e] += xv.x * wv.x + xv.y * wv.y + xv.z * wv.z + xv.w * wv.w;
        }
    }
#pragma unroll
    for (int off = 16; off; off >>= 1)
#pragma unroll
        for (int e = 0; e < NE; e++) acc[e] += __shfl_xor_sync(0xffffffffu, acc[e], off);

    if (lane == 0) {
        int i0 = 0; float v0 = acc[0];
#pragma unroll
        for (int e = 1; e < NE; e++) if (acc[e] > v0) { v0 = acc[e]; i0 = e; }
        int i1 = -1; float v1 = -1e30f;
#pragma unroll
        for (int e = 0; e < NE; e++) if (e != i0 && acc[e] > v1) { v1 = acc[e]; i1 = e; }
        float w0 = 1.f / (1.f + expf(v1 - v0));
        g_pw[2*t] = w0;  g_pw[2*t+1] = 1.f - w0;
        int pos0 = atomicAdd(&g_cnt[i0], 1);
        g_list[i0 * NP + pos0] = 2*t;
        int pos1 = atomicAdd(&g_cnt[i1], 1);
        g_list[i1 * NP + pos1] = 2*t+1;
    }
}

// ============================================================
// GEMM1: gathered xh (fp16) x tiled w1h + SwiGLU -> g_act (fp16)
// ============================================================
__global__ __launch_bounds__(256, 2) void gemm1_tc()
{
    const int e = blockIdx.z;
    const int cnt = g_cnt[e];
    const int m0 = blockIdx.y * 128;
    if (m0 >= cnt) return;
    const int bx = blockIdx.x;
    const int n0a = bx * 64;

    extern __shared__ char smem[];
    int* sp = (int*)(smem + SM_SP);
    const uint32_t sb = (uint32_t)__cvta_generic_to_shared(smem);

    const int tid = threadIdx.x;
    const int w = tid >> 5, lane = tid & 31;

    if (tid < 128) { int m = m0 + tid; sp[tid] = (m < cnt) ? g_list[e * NP + m] : -1; }
    __syncthreads();

    const int m_row = tid >> 1;
    const int pa = sp[m_row];
    const __half* asrc = g_xh + (size_t)(pa >= 0 ? (pa >> 1) : 0) * HD;
    const int mt = m_row >> 4, row = m_row & 7, mh = (m_row >> 3) & 1;
    uint32_t dstA[2]; int srcA[2];
#pragma unroll
    for (int s = 0; s < 2; s++) {
        int g8 = (tid & 1) * 2 + s;
        int kt = g8 >> 1, kh8 = g8 & 1;
        int mat = mh + 2 * kh8;
        dstA[s] = (uint32_t)((mt * 2 + kt) * 512 + mat * 128 + row * 16);
        srcA[s] = g8 * 8;
    }
    const __half* wsrc = g_w1h + (((size_t)e * G1_BX + bx) * G1_NC) * 4096;

    float acc[2][8][4];
#pragma unroll
    for (int i = 0; i < 2; i++)
#pragma unroll
        for (int n = 0; n < 8; n++)
#pragma unroll
            for (int c2 = 0; c2 < 4; c2++) acc[i][n][c2] = 0.f;

#pragma unroll
    for (int pc = 0; pc < 3; pc++) {
        uint32_t ab = sb + SM_A(pc), bb = sb + SM_B(pc);
#pragma unroll
        for (int s = 0; s < 2; s++) {
            cpa16(ab + dstA[s], asrc + pc * 32 + srcA[s]);
            cpa16(bb + tid * 32 + s * 16, wsrc + (size_t)pc * 4096 + tid * 16 + s * 8);
        }
        CP_COMMIT();
    }

    const int mtg0 = (w >> 1) * 2;
    const int ntp0 = (w & 1) * 4;
    const uint32_t loff = (uint32_t)((lane >> 3) * 128 + (lane & 7) * 16);

    const int NC = G1_NC;
    for (int c = 0; c < NC; c++) {
        CP_WAIT2();
        __syncthreads();
        // issue chunk c+3 into stage (c+3)&3 (freed: compute of c-1 done before the sync)
        if (c + 3 < NC) {
            const int nc2 = c + 3;
            uint32_t ab2 = sb + SM_A(nc2 & (NSTG-1)), bb2 = sb + SM_B(nc2 & (NSTG-1));
#pragma unroll
            for (int s = 0; s < 2; s++) {
                cpa16(ab2 + dstA[s], asrc + nc2 * 32 + srcA[s]);
                cpa16(bb2 + tid * 32 + s * 16, wsrc + (size_t)nc2 * 4096 + tid * 16 + s * 8);
            }
        }
        CP_COMMIT();
        const int st = c & (NSTG - 1);
        const uint32_t ab = sb + SM_A(st), bb = sb + SM_B(st);
#pragma unroll
        for (int kt = 0; kt < 2; kt++) {
            uint32_t A0[4], A1[4];
            ldsm4(A0, ab + (uint32_t)(((mtg0 + 0) * 2 + kt) * 512) + loff);
            ldsm4(A1, ab + (uint32_t)(((mtg0 + 1) * 2 + kt) * 512) + loff);
#pragma unroll
            for (int j = 0; j < 4; j++) {
                uint32_t B[4];
                ldsm4(B, bb + (uint32_t)(((ntp0 + j) * 2 + kt) * 512) + loff);
                mma16(acc[0][2*j],   A0[0], A0[1], A0[2], A0[3], B[0], B[1]);
                mma16(acc[1][2*j],   A1[0], A1[1], A1[2], A1[3], B[0], B[1]);
                mma16(acc[0][2*j+1], A0[0], A0[1], A0[2], A0[3], B[2], B[3]);
                mma16(acc[1][2*j+1], A1[0], A1[1], A1[2], A1[3], B[2], B[3]);
            }
        }
    }

    // epilogue: nt even = gate, odd = up -> silu(gate)*up, fp16 out
    const int gid = lane >> 2, ctg = lane & 3;
#pragma unroll
    for (int mt2 = 0; mt2 < 2; mt2++) {
        int r0 = (w >> 1) * 32 + mt2 * 16 + gid;
        int p0 = sp[r0];
        int p1 = sp[r0 + 8];
#pragma unroll
        for (int j = 0; j < 4; j++) {
            float* g = acc[mt2][2 * j];
            float* u = acc[mt2][2 * j + 1];
            int col = n0a + ((w & 1) * 4 + j) * 8 + 2 * ctg;
            if (p0 >= 0) {
                float h0 = u[0] * g[0] / (1.f + expf(-g[0]));
                float h1 = u[1] * g[1] / (1.f + expf(-g[1]));
                *(__half2*)(g_act + (size_t)p0 * ID + col) = __floats2half2_rn(h0, h1);
            }
            if (p1 >= 0) {
                float h2 = u[2] * g[2] / (1.f + expf(-g[2]));
                float h3 = u[3] * g[3] / (1.f + expf(-g[3]));
                *(__half2*)(g_act + (size_t)p1 * ID + col) = __floats2half2_rn(h2, h3);
            }
        }
    }
}

// ============================================================
// GEMM2: gathered g_act (fp16) x tiled w2h -> g_y2h (fp16)
// ============================================================
__global__ __launch_bounds__(256, 2) void gemm2_tc()
{
    const int e = blockIdx.z;
    const int cnt = g_cnt[e];
    const int m0 = blockIdx.y * 128;
    if (m0 >= cnt) return;
    const int bx = blockIdx.x;
    const int n0 = bx * 128;

    extern __shared__ char smem[];
    int* sp = (int*)(smem + SM_SP);
    const uint32_t sb = (uint32_t)__cvta_generic_to_shared(smem);

    const int tid = threadIdx.x;
    const int w = tid >> 5, lane = tid & 31;

    if (tid < 128) { int m = m0 + tid; sp[tid] = (m < cnt) ? g_list[e * NP + m] : -1; }
    __syncthreads();

    const int m_row = tid >> 1;
    const int pa = sp[m_row];
    const __half* asrc = g_act + (size_t)(pa >= 0 ? pa : 0) * ID;
    const int mt = m_row >> 4, row = m_row & 7, mh = (m_row >> 3) & 1;
    uint32_t dstA[2]; int srcA[2];
#pragma unroll
    for (int s = 0; s < 2; s++) {
        int g8 = (tid & 1) * 2 + s;
        int kt = g8 >> 1, kh8 = g8 & 1;
        int mat = mh + 2 * kh8;
        dstA[s] = (uint32_t)((mt * 2 + kt) * 512 + mat * 128 + row * 16);
        srcA[s] = g8 * 8;
    }
    const __half* wsrc = g_w2h + (((size_t)e * G2_BX + bx) * G2_NC) * 4096;

    float acc[2][8][4];
#pragma unroll
    for (int i = 0; i < 2; i++)
#pragma unroll
        for (int n = 0; n < 8; n++)
#pragma unroll
            for (int c2 = 0; c2 < 4; c2++) acc[i][n][c2] = 0.f;

#pragma unroll
    for (int pc = 0; pc < 3; pc++) {
        uint32_t ab = sb + SM_A(pc), bb = sb + SM_B(pc);
#pragma unroll
        for (int s = 0; s < 2; s++) {
            cpa16(ab + dstA[s], asrc + pc * 32 + srcA[s]);
            cpa16(bb + tid * 32 + s * 16, wsrc + (size_t)pc * 4096 + tid * 16 + s * 8);
        }
        CP_COMMIT();
    }

    const int mtg0 = (w >> 1) * 2;
    const int ntp0 = (w & 1) * 4;
    const uint32_t loff = (uint32_t)((lane >> 3) * 128 + (lane & 7) * 16);

    const int NC = G2_NC;
    for (int c = 0; c < NC; c++) {
        CP_WAIT2();
        __syncthreads();
        if (c + 3 < NC) {
            const int nc2 = c + 3;
            uint32_t ab2 = sb + SM_A(nc2 & (NSTG-1)), bb2 = sb + SM_B(nc2 & (NSTG-1));
#pragma unroll
            for (int s = 0; s < 2; s++) {
                cpa16(ab2 + dstA[s], asrc + nc2 * 32 + srcA[s]);
                cpa16(bb2 + tid * 32 + s * 16, wsrc + (size_t)nc2 * 4096 + tid * 16 + s * 8);
            }
        }
        CP_COMMIT();
        const int st = c & (NSTG - 1);
        const uint32_t ab = sb + SM_A(st), bb = sb + SM_B(st);
#pragma unroll
        for (int kt = 0; kt < 2; kt++) {
            uint32_t A0[4], A1[4];
            ldsm4(A0, ab + (uint32_t)(((mtg0 + 0) * 2 + kt) * 512) + loff);
            ldsm4(A1, ab + (uint32_t)(((mtg0 + 1) * 2 + kt) * 512) + loff);
#pragma unroll
            for (int j = 0; j < 4; j++) {
                uint32_t B[4];
                ldsm4(B, bb + (uint32_t)(((ntp0 + j) * 2 + kt) * 512) + loff);
                mma16(acc[0][2*j],   A0[0], A0[1], A0[2], A0[3], B[0], B[1]);
                mma16(acc[1][2*j],   A1[0], A1[1], A1[2], A1[3], B[0], B[1]);
                mma16(acc[0][2*j+1], A0[0], A0[1], A0[2], A0[3], B[2], B[3]);
                mma16(acc[1][2*j+1], A1[0], A1[1], A1[2], A1[3], B[2], B[3]);
            }
        }
    }

    const int gid = lane >> 2, ctg = lane & 3;
#pragma unroll
    for (int mt2 = 0; mt2 < 2; mt2++) {
        int r0 = (w >> 1) * 32 + mt2 * 16 + gid;
        int p0 = sp[r0];
        int p1 = sp[r0 + 8];
#pragma unroll
        for (int n = 0; n < 8; n++) {
            int col = n0 + ((w & 1) * 8 + n) * 8 + 2 * ctg;
            if (p0 >= 0)
                *(__half2*)(g_y2h + (size_t)p0 * HD + col) = __floats2half2_rn(acc[mt2][n][0], acc[mt2][n][1]);
            if (p1 >= 0)
                *(__half2*)(g_y2h + (size_t)p1 * HD + col) = __floats2half2_rn(acc[mt2][n][2], acc[mt2][n][3]);
        }
    }
}

// ============================================================
// combine: out[t] = w0*y2[2t] + w1*y2[2t+1] (fp16 in, fp32 out)
// ============================================================
__global__ __launch_bounds__(256) void combine_kernel(float* __restrict__ out)
{
    size_t i = (size_t)blockIdx.x * blockDim.x + threadIdx.x;  // over NT*HD/4
    const size_t tot = (size_t)NT * HD / 4;
    if (i >= tot) return;
    int t = (int)(i / (HD/4));
    int r = (int)(i % (HD/4));
    float w0 = g_pw[2*t], w1v = g_pw[2*t+1];
    const uint2* ya = reinterpret_cast<const uint2*>(g_y2h + (size_t)(2*t) * HD) + r;
    const uint2* yb = reinterpret_cast<const uint2*>(g_y2h + (size_t)(2*t+1) * HD) + r;
    uint2 av = *ya, bv = *yb;
    float2 a0 = __half22float2(*(__half2*)&av.x);
    float2 a1 = __half22float2(*(__half2*)&av.y);
    float2 b0 = __half22float2(*(__half2*)&bv.x);
    float2 b1 = __half22float2(*(__half2*)&bv.y);
    float4 o;
    o.x = w0*a0.x + w1v*b0.x;
    o.y = w0*a0.y + w1v*b0.y;
    o.z = w0*a1.x + w1v*b1.x;
    o.w = w0*a1.y + w1v*b1.y;
    reinterpret_cast<float4*>(out)[i] = o;
}

// ============================================================
extern "C" void kernel_launch(void* const* d_in, const int* in_sizes, int n_in,
                              void* d_out, int out_size)
{
    const float* x  = (const float*)d_in[0];
    const float* rw = (const float*)d_in[1];
    const float* w1 = (const float*)d_in[2];
    const float* w2 = (const float*)d_in[3];
    float* out = (float*)d_out;

    cudaFuncSetAttribute(gemm1_tc, cudaFuncAttributeMaxDynamicSharedMemorySize, SMEM_BYTES);
    cudaFuncSetAttribute(gemm2_tc, cudaFuncAttributeMaxDynamicSharedMemorySize, SMEM_BYTES);

    prep_w1<<<dim3(G1_NC, G1_BX, NE), 256>>>(w1);   // also zeroes g_cnt
    prep_w2<<<dim3(G2_NC, G2_BX, NE), 256>>>(w2);
    router_kernel<<<NT/8, 256>>>(x, rw);            // logits + scatter + x->fp16
    gemm1_tc<<<dim3(G1_BX, NP/128, NE), 256, SMEM_BYTES>>>();
    gemm2_tc<<<dim3(G2_BX, NP/128, NE), 256, SMEM_BYTES>>>();
    combine_kernel<<<(unsigned)(((size_t)NT*HD/4 + 255)/256), 256>>>(out);
}